// round 12
// baseline (speedup 1.0000x reference)
#include <cuda_runtime.h>

// ---------------------------------------------------------------------------
// QWTForward collapses to: D = bicubic_down2(image); out[q][b] = D * (S_a*S_b)
// where S_* are the sums of the 4 filter tap arrays (reference's filt(x,h)
// is exactly x * sum(h), and downsample is linear).
//
// CRITICAL: sum(gh), sum(fl), sum(fh) are analytically-zero rounding residue;
// outputs 1-3 are proportional to it. Summation must be SEQUENTIAL per filter
// (matches jnp.sum rounding). Unrolling keeps the add order while issuing the
// 30 loads in parallel.
//
// R12: PERSISTENT kernel — one wave (148 SMs x 4 blocks x 512 thr), each
// block grid-strides over ~10.4 chunks. Prologue paid once per block (592x
// instead of 6144x), no CTA churn across waves, and iteration i+1's loads
// overlap iteration i's stores inside each warp. Body arithmetic/coalescing
// identical to the measured-best R1 form -> bit-identical output.
// ---------------------------------------------------------------------------

__global__ __launch_bounds__(512) void qwt_persist_kernel(
    const float* __restrict__ img,
    const float* __restrict__ gl, const float* __restrict__ gh,
    const float* __restrict__ fl, const float* __restrict__ fh,
    float* __restrict__ out, int NC, int L, unsigned total_px) {

    __shared__ float s4[4];
    __shared__ __align__(16) float sc[16];

    // ---- prologue: once per block (threads 0-3 load, 0-15 combine) ----
    if (threadIdx.x < 32) {
        const int t = threadIdx.x;
        if (t < 4) {
            const float* F = (t == 0) ? gl : (t == 1) ? gh : (t == 2) ? fl : fh;
            float s = 0.f;
            if (L == 30) {
                float a[30];
#pragma unroll
                for (int i = 0; i < 30; i++) a[i] = __ldg(F + i);
#pragma unroll
                for (int i = 0; i < 30; i++) s += a[i];
            } else {
                for (int i = 0; i < L; i++) s += F[i];
            }
            s4[t] = s;
        }
        __syncwarp();
        if (t < 16) {
            const int q = t >> 2, b = t & 3;
            const int fi = ((b & 1) << 1) | (q >> 1);
            const int si = ((b >> 1) << 1) | (q & 1);
            sc[t] = s4[fi] * s4[si];
        }
    }
    __syncthreads();

    const float4* scv = (const float4*)sc;
    const float4 sv0 = scv[0], sv1 = scv[1], sv2 = scv[2], sv3 = scv[3];

    const float w0 = -0.09375f;
    const float w1 =  0.59375f;
    const size_t plane = 256u * 256u;
    const size_t QS    = (size_t)(NC / 3) * 12u * plane;  // elems per output tensor
    const unsigned stride = gridDim.x * 512u;

    for (unsigned idx = blockIdx.x * 512u + threadIdx.x; idx < total_px;
         idx += stride) {
        const unsigned x  = idx & 255u;
        const unsigned y  = (idx >> 8) & 255u;
        const unsigned nc = idx >> 16;

        const float* src = img + (size_t)nc * (512u * 512u);

        const int xb = 2 * (int)x - 1;
        const int yb = 2 * (int)y - 1;
        const int x0 = max(xb, 0);
        const int x1 = xb + 1;
        const int x2 = xb + 2;
        const int x3 = min(xb + 3, 511);
        const int y0 = max(yb, 0);
        const int y3 = min(yb + 3, 511);

        const float* r0 = src + (size_t)y0 * 512;
        const float* r1 = src + (size_t)(yb + 1) * 512;
        const float* r2 = src + (size_t)(yb + 2) * 512;
        const float* r3 = src + (size_t)y3 * 512;

        float h0 = w0 * (__ldg(r0 + x0) + __ldg(r0 + x3)) + w1 * (__ldg(r0 + x1) + __ldg(r0 + x2));
        float h1 = w0 * (__ldg(r1 + x0) + __ldg(r1 + x3)) + w1 * (__ldg(r1 + x1) + __ldg(r1 + x2));
        float h2 = w0 * (__ldg(r2 + x0) + __ldg(r2 + x3)) + w1 * (__ldg(r2 + x1) + __ldg(r2 + x2));
        float h3 = w0 * (__ldg(r3 + x0) + __ldg(r3 + x3)) + w1 * (__ldg(r3 + x1) + __ldg(r3 + x2));

        const float dval = w0 * (h0 + h3) + w1 * (h1 + h2);

        const unsigned n = nc / 3u;
        const unsigned c = nc - 3u * n;
        const size_t base = ((size_t)(n * 12u + c)) * plane + (size_t)y * 256u + x;

        float* o0 = out + base;
        float* o1 = out + base + QS;
        float* o2 = out + base + 2 * QS;
        float* o3 = out + base + 3 * QS;
        o0[0]         = dval * sv0.x;
        o0[3 * plane] = dval * sv0.y;
        o0[6 * plane] = dval * sv0.z;
        o0[9 * plane] = dval * sv0.w;
        o1[0]         = dval * sv1.x;
        o1[3 * plane] = dval * sv1.y;
        o1[6 * plane] = dval * sv1.z;
        o1[9 * plane] = dval * sv1.w;
        o2[0]         = dval * sv2.x;
        o2[3 * plane] = dval * sv2.y;
        o2[6 * plane] = dval * sv2.z;
        o2[9 * plane] = dval * sv2.w;
        o3[0]         = dval * sv3.x;
        o3[3 * plane] = dval * sv3.y;
        o3[6 * plane] = dval * sv3.z;
        o3[9 * plane] = dval * sv3.w;
    }
}

extern "C" void kernel_launch(void* const* d_in, const int* in_sizes, int n_in,
                              void* d_out, int out_size) {
    const float* img = (const float*)d_in[0];
    const float* gl  = (const float*)d_in[1];
    const float* gh  = (const float*)d_in[2];
    const float* fl  = (const float*)d_in[3];
    const float* fh  = (const float*)d_in[4];

    const int L  = in_sizes[1];                 // filter length (30)
    const int NC = in_sizes[0] / (512 * 512);   // N*3 = 48 channels
    const unsigned total_px = (unsigned)NC * 256u * 256u;

    // one wave: 148 SMs x 4 blocks x 512 threads
    int grid = 148 * 4;
    const int chunks = (int)(total_px / 512u);
    if (grid > chunks) grid = chunks;

    qwt_persist_kernel<<<grid, 512>>>(img, gl, gh, fl, fh,
                                      (float*)d_out, NC, L, total_px);
}

// round 13
// speedup vs baseline: 1.1805x; 1.1805x over previous
#include <cuda_runtime.h>

// ---------------------------------------------------------------------------
// QWTForward collapses to: D = bicubic_down2(image); out[q][b] = D * (S_a*S_b)
// where S_* are the sums of the 4 filter tap arrays (reference's filt(x,h)
// is exactly x * sum(h), and downsample is linear).
//
// CRITICAL: sum(gh), sum(fl), sum(fh) are analytically-zero rounding residue;
// outputs 1-3 are proportional to it. Summation must be SEQUENTIAL per filter
// (matches jnp.sum rounding). Unrolling keeps the add order while issuing the
// 30 loads in parallel.
//
// R13 = R10 (measured best: 256-thr fused, minimal warp-0 prologue, LATE
// barrier, R1 body) + __stcs streaming stores ONLY. Outputs are write-once-
// never-read; evict-first keeps the 201MB write stream from thrashing the
// input's L2 read-reuse set. Single isolated change vs the 46.5us best.
// ---------------------------------------------------------------------------

__global__ __launch_bounds__(256) void qwt_fused_kernel(
    const float* __restrict__ img,
    const float* __restrict__ gl, const float* __restrict__ gh,
    const float* __restrict__ fl, const float* __restrict__ fh,
    float* __restrict__ out, int NC, int L) {

    __shared__ float s4[4];
    __shared__ __align__(16) float sc[16];

    // ---- prologue: warp 0 only (threads 0-3 load, 0-15 combine) ----
    if (threadIdx.x < 32) {
        const int t = threadIdx.x;
        if (t < 4) {
            const float* F = (t == 0) ? gl : (t == 1) ? gh : (t == 2) ? fl : fh;
            float s = 0.f;
            if (L == 30) {
                float a[30];
#pragma unroll
                for (int i = 0; i < 30; i++) a[i] = __ldg(F + i);
#pragma unroll
                for (int i = 0; i < 30; i++) s += a[i];
            } else {
                for (int i = 0; i < L; i++) s += F[i];
            }
            s4[t] = s;
        }
        __syncwarp();
        if (t < 16) {
            const int q = t >> 2, b = t & 3;
            const int fi = ((b & 1) << 1) | (q >> 1);
            const int si = ((b >> 1) << 1) | (q & 1);
            sc[t] = s4[fi] * s4[si];
        }
    }

    // ---- body: one output pixel of D per thread (independent of sc) ----
    const unsigned idx = blockIdx.x * 256u + threadIdx.x;
    const unsigned x  = idx & 255u;
    const unsigned y  = (idx >> 8) & 255u;
    const unsigned nc = idx >> 16;

    const float* src = img + (size_t)nc * (512u * 512u);

    const int xb = 2 * (int)x - 1;
    const int yb = 2 * (int)y - 1;
    const int x0 = max(xb, 0);
    const int x1 = xb + 1;
    const int x2 = xb + 2;
    const int x3 = min(xb + 3, 511);
    const int y0 = max(yb, 0);
    const int y3 = min(yb + 3, 511);

    const float w0 = -0.09375f;
    const float w1 =  0.59375f;

    const float* r0 = src + (size_t)y0 * 512;
    const float* r1 = src + (size_t)(yb + 1) * 512;
    const float* r2 = src + (size_t)(yb + 2) * 512;
    const float* r3 = src + (size_t)y3 * 512;

    float h0 = w0 * (__ldg(r0 + x0) + __ldg(r0 + x3)) + w1 * (__ldg(r0 + x1) + __ldg(r0 + x2));
    float h1 = w0 * (__ldg(r1 + x0) + __ldg(r1 + x3)) + w1 * (__ldg(r1 + x1) + __ldg(r1 + x2));
    float h2 = w0 * (__ldg(r2 + x0) + __ldg(r2 + x3)) + w1 * (__ldg(r2 + x1) + __ldg(r2 + x2));
    float h3 = w0 * (__ldg(r3 + x0) + __ldg(r3 + x3)) + w1 * (__ldg(r3 + x1) + __ldg(r3 + x2));

    const float dval = w0 * (h0 + h3) + w1 * (h1 + h2);

    // ---- LATE barrier: prologue latency hidden under the body's loads ----
    __syncthreads();

    const unsigned n = nc / 3u;
    const unsigned c = nc - 3u * n;
    const size_t plane = 256u * 256u;
    const size_t base  = ((size_t)(n * 12u + c)) * plane + (size_t)y * 256u + x;
    const size_t QS    = (size_t)(NC / 3) * 12u * plane;  // elements per output tensor

    const float4* scv = (const float4*)sc;
#pragma unroll
    for (int q = 0; q < 4; q++) {
        const float4 sv = scv[q];
        float* o = out + base + (size_t)q * QS;
        __stcs(o,             dval * sv.x);
        __stcs(o + 3 * plane, dval * sv.y);
        __stcs(o + 6 * plane, dval * sv.z);
        __stcs(o + 9 * plane, dval * sv.w);
    }
}

extern "C" void kernel_launch(void* const* d_in, const int* in_sizes, int n_in,
                              void* d_out, int out_size) {
    const float* img = (const float*)d_in[0];
    const float* gl  = (const float*)d_in[1];
    const float* gh  = (const float*)d_in[2];
    const float* fl  = (const float*)d_in[3];
    const float* fh  = (const float*)d_in[4];

    const int L  = in_sizes[1];                 // filter length (30)
    const int NC = in_sizes[0] / (512 * 512);   // N*3 = 48 channels

    const int total_threads = NC * 256 * 256;   // one per downsampled pixel
    qwt_fused_kernel<<<total_threads / 256, 256>>>(img, gl, gh, fl, fh,
                                                   (float*)d_out, NC, L);
}

// round 14
// speedup vs baseline: 1.1813x; 1.0007x over previous
#include <cuda_runtime.h>

// ---------------------------------------------------------------------------
// QWTForward collapses to: D = bicubic_down2(image); out[q][b] = D * (S_a*S_b)
// where S_* are the sums of the 4 filter tap arrays (reference's filt(x,h)
// is exactly x * sum(h), and downsample is linear).
//
// CRITICAL: sum(gh), sum(fl), sum(fh) are analytically-zero rounding residue;
// outputs 1-3 are proportional to it. Summation must be SEQUENTIAL per filter
// (matches jnp.sum rounding). Unrolling keeps the add order while issuing the
// 30 loads in parallel.
//
// R14 = R13 (stcs streaming stores, minimal warp-0 prologue, LATE barrier,
// R1 body — best, 45.6us) + R11's 512-thread blocks (half the prologue/
// barrier episodes, same occupancy shape, identical coalescing/arithmetic).
// ---------------------------------------------------------------------------

__global__ __launch_bounds__(512) void qwt_fused_kernel(
    const float* __restrict__ img,
    const float* __restrict__ gl, const float* __restrict__ gh,
    const float* __restrict__ fl, const float* __restrict__ fh,
    float* __restrict__ out, int NC, int L) {

    __shared__ float s4[4];
    __shared__ __align__(16) float sc[16];

    // ---- prologue: warp 0 only (threads 0-3 load, 0-15 combine) ----
    if (threadIdx.x < 32) {
        const int t = threadIdx.x;
        if (t < 4) {
            const float* F = (t == 0) ? gl : (t == 1) ? gh : (t == 2) ? fl : fh;
            float s = 0.f;
            if (L == 30) {
                float a[30];
#pragma unroll
                for (int i = 0; i < 30; i++) a[i] = __ldg(F + i);
#pragma unroll
                for (int i = 0; i < 30; i++) s += a[i];
            } else {
                for (int i = 0; i < L; i++) s += F[i];
            }
            s4[t] = s;
        }
        __syncwarp();
        if (t < 16) {
            const int q = t >> 2, b = t & 3;
            const int fi = ((b & 1) << 1) | (q >> 1);
            const int si = ((b >> 1) << 1) | (q & 1);
            sc[t] = s4[fi] * s4[si];
        }
    }

    // ---- body: one output pixel of D per thread (independent of sc) ----
    const unsigned idx = blockIdx.x * 512u + threadIdx.x;
    const unsigned x  = idx & 255u;
    const unsigned y  = (idx >> 8) & 255u;
    const unsigned nc = idx >> 16;

    const float* src = img + (size_t)nc * (512u * 512u);

    const int xb = 2 * (int)x - 1;
    const int yb = 2 * (int)y - 1;
    const int x0 = max(xb, 0);
    const int x1 = xb + 1;
    const int x2 = xb + 2;
    const int x3 = min(xb + 3, 511);
    const int y0 = max(yb, 0);
    const int y3 = min(yb + 3, 511);

    const float w0 = -0.09375f;
    const float w1 =  0.59375f;

    const float* r0 = src + (size_t)y0 * 512;
    const float* r1 = src + (size_t)(yb + 1) * 512;
    const float* r2 = src + (size_t)(yb + 2) * 512;
    const float* r3 = src + (size_t)y3 * 512;

    float h0 = w0 * (__ldg(r0 + x0) + __ldg(r0 + x3)) + w1 * (__ldg(r0 + x1) + __ldg(r0 + x2));
    float h1 = w0 * (__ldg(r1 + x0) + __ldg(r1 + x3)) + w1 * (__ldg(r1 + x1) + __ldg(r1 + x2));
    float h2 = w0 * (__ldg(r2 + x0) + __ldg(r2 + x3)) + w1 * (__ldg(r2 + x1) + __ldg(r2 + x2));
    float h3 = w0 * (__ldg(r3 + x0) + __ldg(r3 + x3)) + w1 * (__ldg(r3 + x1) + __ldg(r3 + x2));

    const float dval = w0 * (h0 + h3) + w1 * (h1 + h2);

    // ---- LATE barrier: prologue latency hidden under the body's loads ----
    __syncthreads();

    const unsigned n = nc / 3u;
    const unsigned c = nc - 3u * n;
    const size_t plane = 256u * 256u;
    const size_t base  = ((size_t)(n * 12u + c)) * plane + (size_t)y * 256u + x;
    const size_t QS    = (size_t)(NC / 3) * 12u * plane;  // elements per output tensor

    const float4* scv = (const float4*)sc;
#pragma unroll
    for (int q = 0; q < 4; q++) {
        const float4 sv = scv[q];
        float* o = out + base + (size_t)q * QS;
        __stcs(o,             dval * sv.x);
        __stcs(o + 3 * plane, dval * sv.y);
        __stcs(o + 6 * plane, dval * sv.z);
        __stcs(o + 9 * plane, dval * sv.w);
    }
}

extern "C" void kernel_launch(void* const* d_in, const int* in_sizes, int n_in,
                              void* d_out, int out_size) {
    const float* img = (const float*)d_in[0];
    const float* gl  = (const float*)d_in[1];
    const float* gh  = (const float*)d_in[2];
    const float* fl  = (const float*)d_in[3];
    const float* fh  = (const float*)d_in[4];

    const int L  = in_sizes[1];                 // filter length (30)
    const int NC = in_sizes[0] / (512 * 512);   // N*3 = 48 channels

    const int total_threads = NC * 256 * 256;   // one per downsampled pixel
    qwt_fused_kernel<<<total_threads / 512, 512>>>(img, gl, gh, fl, fh,
                                                   (float*)d_out, NC, L);
}